// round 15
// baseline (speedup 1.0000x reference)
#include <cuda_runtime.h>
#include <cuda_bf16.h>
#include <math.h>
#include <stdint.h>

#define BATCH 4
#define SEQ   2048
#define DIM   256
#define NHEAD 4
#define HDIM  64
#define NROWS (BATCH*NHEAD*SEQ)

// ---- scratch (allocation-free: device globals) ----
static __device__ __nv_bfloat16 g_Qh[BATCH*NHEAD*SEQ*HDIM];
static __device__ __nv_bfloat16 g_Qm[BATCH*NHEAD*SEQ*HDIM];
static __device__ __nv_bfloat16 g_Ql[BATCH*NHEAD*SEQ*HDIM];
static __device__ __nv_bfloat16 g_Kh[BATCH*NHEAD*SEQ*HDIM];
static __device__ __nv_bfloat16 g_Km[BATCH*NHEAD*SEQ*HDIM];
static __device__ __nv_bfloat16 g_Kl[BATCH*NHEAD*SEQ*HDIM];
static __device__ float g_Qf[BATCH*NHEAD*SEQ*HDIM];   // fp32 (scaled) for FMA heads
static __device__ float g_Kf[BATCH*NHEAD*SEQ*HDIM];
static __device__ float g_V[BATCH*NHEAD*SEQ*HDIM];
static __device__ float g_scores[(size_t)NROWS * SEQ];   // 268 MB
static __device__ float g_mixed[BATCH*SEQ*DIM];
static __device__ float g_gproj[BATCH*DIM];
static __device__ float g_mpart[BATCH*16*DIM];

// ---- order-preserving float<->uint key transform ----
__device__ __forceinline__ unsigned f2k(float f){
    unsigned u = __float_as_uint(f);
    return (u & 0x80000000u) ? ~u : (u | 0x80000000u);
}
__device__ __forceinline__ float k2f(unsigned k){
    return (k & 0x80000000u) ? __uint_as_float(k & 0x7fffffffu)
                             : __uint_as_float(~k);
}

// ---- packed f32x2 FMA helpers (PTX >= 8.6, sm_100 family) ----
__device__ __forceinline__ unsigned long long packdup(float x){
    unsigned long long r;
    unsigned u = __float_as_uint(x);
    asm("mov.b64 %0, {%1, %1};" : "=l"(r) : "r"(u));
    return r;
}
__device__ __forceinline__ void fma2(unsigned long long &c,
                                     unsigned long long a, unsigned long long b){
    asm("fma.rn.f32x2 %0, %1, %2, %0;" : "+l"(c) : "l"(a), "l"(b));
}
__device__ __forceinline__ void unpack2(unsigned long long v, float &x, float &y){
    unsigned lo, hi;
    asm("mov.b64 {%0, %1}, %2;" : "=r"(lo), "=r"(hi) : "l"(v));
    x = __uint_as_float(lo);
    y = __uint_as_float(hi);
}

// ---- mma.sync helpers (baseline PTX, valid on compute_103) ----
__device__ __forceinline__ uint32_t smem_u32(const void* p){
    uint32_t a;
    asm("{ .reg .u64 t; cvta.to.shared.u64 t, %1; cvt.u32.u64 %0, t; }"
        : "=r"(a) : "l"(p));
    return a;
}
#define SW128(o) ((o) ^ (((o) >> 3) & 0x70))

__device__ __forceinline__ void ldsm_x4(uint32_t addr, uint32_t* r){
    asm volatile("ldmatrix.sync.aligned.m8n8.x4.shared.b16 {%0,%1,%2,%3}, [%4];"
        : "=r"(r[0]), "=r"(r[1]), "=r"(r[2]), "=r"(r[3]) : "r"(addr));
}
__device__ __forceinline__ void ldsm_x2(uint32_t addr, uint32_t* r){
    asm volatile("ldmatrix.sync.aligned.m8n8.x2.shared.b16 {%0,%1}, [%2];"
        : "=r"(r[0]), "=r"(r[1]) : "r"(addr));
}
__device__ __forceinline__ void mma16816(float* c, const uint32_t* a, const uint32_t* b){
    asm volatile("mma.sync.aligned.m16n8k16.row.col.f32.bf16.bf16.f32 "
        "{%0,%1,%2,%3}, {%4,%5,%6,%7}, {%8,%9}, {%0,%1,%2,%3};"
        : "+f"(c[0]), "+f"(c[1]), "+f"(c[2]), "+f"(c[3])
        : "r"(a[0]), "r"(a[1]), "r"(a[2]), "r"(a[3]), "r"(b[0]), "r"(b[1]));
}

#define STILE 16384
#define SMMA_SMEM (6*STILE)

// =====================================================================
// HMMA path: one 128x128 score tile via 6-pass triple-bf16-split.
// =====================================================================
__device__ void hmma_scores_tile(char* smem,
    const __nv_bfloat16* __restrict__ Qh, const __nv_bfloat16* __restrict__ Qm,
    const __nv_bfloat16* __restrict__ Ql, const __nv_bfloat16* __restrict__ Kh,
    const __nv_bfloat16* __restrict__ Km, const __nv_bfloat16* __restrict__ Kl,
    float* __restrict__ S, int bh, int m0, int n0)
{
    const int t = threadIdx.x, lane = t & 31, wid = t >> 5;

    const __nv_bfloat16* srcs[6] = {Qh, Qm, Ql, Kh, Km, Kl};
    const int row = t >> 1, half = t & 1;
#pragma unroll
    for (int p = 0; p < 6; p++){
        int br = (p < 3) ? m0 : n0;
        const uint4* src = (const uint4*)(srcs[p] + (((size_t)bh * SEQ) + br + row) * HDIM) + half * 4;
        char* tile = smem + p * STILE;
#pragma unroll
        for (int j = 0; j < 4; j++){
            uint4 v = src[j];
            uint32_t off = row * 128 + (half * 4 + j) * 16;
            *(uint4*)(tile + SW128(off)) = v;
        }
    }
    __syncthreads();

    const uint32_t smem_b = smem_u32(smem);
    const int wm = wid >> 2, wn = wid & 3;

    float acc[4][4][4];
#pragma unroll
    for (int i = 0; i < 4; i++)
#pragma unroll
        for (int j = 0; j < 4; j++)
#pragma unroll
            for (int k = 0; k < 4; k++) acc[i][j][k] = 0.f;

    const int a_t = lane >> 3, a_r = lane & 7;
    const int a_rowoff = (a_t & 1) * 8 + a_r;
    const int a_coloff = (a_t >> 1) * 16;
    const int b_r = lane & 7;
    const int b_coloff = ((lane >> 3) & 1) * 16;

    const int nb[3] = {3, 2, 1};
#pragma unroll
    for (int ai = 0; ai < 3; ai++){
        const uint32_t abase = smem_b + ai * STILE;
#pragma unroll
        for (int ks = 0; ks < 4; ks++){
            const int kb = ks * 32;
            uint32_t a[4][4];
#pragma unroll
            for (int mi = 0; mi < 4; mi++){
                uint32_t off = (uint32_t)(wm * 64 + mi * 16 + a_rowoff) * 128 + kb + a_coloff;
                ldsm_x4(abase + SW128(off), a[mi]);
            }
#pragma unroll
            for (int bi = 0; bi < 3; bi++){
                if (bi >= nb[ai]) break;
                const uint32_t bbase = smem_b + (3 + bi) * STILE;
                uint32_t b[4][2];
#pragma unroll
                for (int nj = 0; nj < 4; nj++){
                    uint32_t off = (uint32_t)(wn * 32 + nj * 8 + b_r) * 128 + kb + b_coloff;
                    ldsm_x2(bbase + SW128(off), b[nj]);
                }
#pragma unroll
                for (int mi = 0; mi < 4; mi++)
#pragma unroll
                    for (int nj = 0; nj < 4; nj++)
                        mma16816(acc[mi][nj], a[mi], b[nj]);
            }
        }
    }

    const int gid = lane >> 2, tig = lane & 3;
    float* Sb = S + (size_t)bh * SEQ * SEQ;
#pragma unroll
    for (int mi = 0; mi < 4; mi++){
        int r0 = m0 + wm * 64 + mi * 16 + gid;
#pragma unroll
        for (int nj = 0; nj < 4; nj++){
            int c = n0 + wn * 32 + nj * 8 + 2 * tig;
            float2 v0 = make_float2(acc[mi][nj][0], acc[mi][nj][1]);
            float2 v1 = make_float2(acc[mi][nj][2], acc[mi][nj][3]);
            *(float2*)(Sb + (size_t)r0 * SEQ + c)       = v0;
            *(float2*)(Sb + (size_t)(r0 + 8) * SEQ + c) = v1;
        }
    }
}

// =====================================================================
// FMA path: one 128x128 score tile, fp32 via packed f32x2 FMA.
// =====================================================================
__device__ void fma_scores_tile(char* smem_raw,
    const float* __restrict__ Qf, const float* __restrict__ Kf,
    float* __restrict__ S, int bh, int m0, int n0)
{
    float (*As)[132] = reinterpret_cast<float(*)[132]>(smem_raw);
    float (*Bs)[132] = reinterpret_cast<float(*)[132]>(smem_raw + 32 * 132 * sizeof(float));
    const float* A = Qf + (size_t)bh * SEQ * HDIM;
    const float* B = Kf + (size_t)bh * SEQ * HDIM;
    const int tid = threadIdx.x;
    const int tx = tid & 15, ty = tid >> 4;
    const int lm = tid >> 1, lk4 = tid & 1;

    const float* Ag = A + (size_t)(m0 + lm) * HDIM + lk4 * 4;
    const float* Bg = B + (size_t)(n0 + lm) * HDIM + lk4 * 4;

    unsigned long long acc2[8][4];
#pragma unroll
    for (int i = 0; i < 8; i++)
#pragma unroll
        for (int j = 0; j < 4; j++) acc2[i][j] = 0ull;

#pragma unroll
    for (int it = 0; it < 2; it++){
        int k0 = it * 32;
        float4 pa[4], pb[4];
#pragma unroll
        for (int kk = 0; kk < 4; kk++){
            pa[kk] = *(const float4*)(Ag + k0 + kk * 8);
            pb[kk] = *(const float4*)(Bg + k0 + kk * 8);
        }
        __syncthreads();
#pragma unroll
        for (int kk = 0; kk < 4; kk++){
            int kc = lk4 * 4 + kk * 8;
            As[kc+0][lm] = pa[kk].x; As[kc+1][lm] = pa[kk].y;
            As[kc+2][lm] = pa[kk].z; As[kc+3][lm] = pa[kk].w;
            Bs[kc+0][lm] = pb[kk].x; Bs[kc+1][lm] = pb[kk].y;
            Bs[kc+2][lm] = pb[kk].z; Bs[kc+3][lm] = pb[kk].w;
        }
        __syncthreads();
#pragma unroll
        for (int kk = 0; kk < 32; kk++){
            float4 a0 = *(const float4*)&As[kk][ty * 4];
            float4 a1 = *(const float4*)&As[kk][64 + ty * 4];
            ulonglong2 b0 = *(const ulonglong2*)&Bs[kk][tx * 4];
            ulonglong2 b1 = *(const ulonglong2*)&Bs[kk][64 + tx * 4];
            unsigned long long bv[4] = {b0.x, b0.y, b1.x, b1.y};
            float avf[8] = {a0.x, a0.y, a0.z, a0.w, a1.x, a1.y, a1.z, a1.w};
            unsigned long long av[8];
#pragma unroll
            for (int i = 0; i < 8; i++) av[i] = packdup(avf[i]);
#pragma unroll
            for (int i = 0; i < 8; i++)
#pragma unroll
                for (int j = 0; j < 4; j++)
                    fma2(acc2[i][j], av[i], bv[j]);
        }
    }

    float* Sb = S + (size_t)bh * SEQ * SEQ;
#pragma unroll
    for (int ii = 0; ii < 8; ii++){
        int r = m0 + ((ii < 4) ? (ty * 4 + ii) : (64 + ty * 4 + ii - 4));
#pragma unroll
        for (int jj = 0; jj < 2; jj++){
            int c = n0 + jj * 64 + tx * 4;
            float4 v;
            unpack2(acc2[ii][jj*2+0], v.x, v.y);
            unpack2(acc2[ii][jj*2+1], v.z, v.w);
            *(float4*)(Sb + (size_t)r * SEQ + c) = v;
        }
    }
}

// =====================================================================
// Hybrid scores kernel: even blockIdx.x -> HMMA (heads 0-7),
// odd -> fp32 FMA (heads 8-15). Monolithic launch (full waves).
// =====================================================================
__global__ void __launch_bounds__(256, 2) scores_hybrid_kernel(
    const __nv_bfloat16* __restrict__ Qh, const __nv_bfloat16* __restrict__ Qm,
    const __nv_bfloat16* __restrict__ Ql, const __nv_bfloat16* __restrict__ Kh,
    const __nv_bfloat16* __restrict__ Km, const __nv_bfloat16* __restrict__ Kl,
    const float* __restrict__ Qf, const float* __restrict__ Kf,
    float* __restrict__ S)
{
    extern __shared__ char smem[];
    const int type = blockIdx.x & 1;
    const int n0 = (blockIdx.x >> 1) * 128;
    const int m0 = blockIdx.y * 128;
    if (type == 0){
        hmma_scores_tile(smem, Qh, Qm, Ql, Kh, Km, Kl, S, blockIdx.z, m0, n0);
    } else {
        fma_scores_tile(smem, Qf, Kf, S, 8 + blockIdx.z, m0, n0);
    }
}

// =====================================================================
// 64x128 SGEMM tile (BK=32, 256 threads, 4x8 microtile, f32x2 FMA).
// Same k-ordered accumulation chain per output element as the 128-tile
// => bit-identical results. Modes as before.
// =====================================================================
__device__ __forceinline__ void gemm_tile64(
    const float* __restrict__ A, const float* __restrict__ B,
    const float* __restrict__ bias, float* __restrict__ C,
    int K, int N, float alpha, float bscale, int m0, int n0, int mode,
    __nv_bfloat16* __restrict__ o1, __nv_bfloat16* __restrict__ o2,
    __nv_bfloat16* __restrict__ o3)
{
    __shared__ float As[32][68];
    __shared__ float Bs[32][132];
    const int tid = threadIdx.x;
    const int tx = tid & 15, ty = tid >> 4;
    const int la = tid >> 2, lka = tid & 3;     // A: row 0..63, col base lka*4
    const int lb = tid >> 1, lkb = tid & 1;     // B: row 0..127, col base lkb*4

    const float* Ag = A + (size_t)(m0 + la) * K + lka * 4;
    const float* Bg = B + (size_t)(n0 + lb) * K + lkb * 4;

    float4 pa[2], pb[4];
#pragma unroll
    for (int kk = 0; kk < 2; kk++) pa[kk] = *(const float4*)(Ag + kk * 16);
#pragma unroll
    for (int kk = 0; kk < 4; kk++) pb[kk] = *(const float4*)(Bg + kk * 8);

    unsigned long long acc2[4][4];
#pragma unroll
    for (int i = 0; i < 4; i++)
#pragma unroll
        for (int j = 0; j < 4; j++) acc2[i][j] = 0ull;

    int k0 = 0;
    for (;;){
        __syncthreads();
#pragma unroll
        for (int kk = 0; kk < 2; kk++){
            int kc = lka * 4 + kk * 16;
            As[kc+0][la] = pa[kk].x; As[kc+1][la] = pa[kk].y;
            As[kc+2][la] = pa[kk].z; As[kc+3][la] = pa[kk].w;
        }
#pragma unroll
        for (int kk = 0; kk < 4; kk++){
            int kc = lkb * 4 + kk * 8;
            Bs[kc+0][lb] = pb[kk].x; Bs[kc+1][lb] = pb[kk].y;
            Bs[kc+2][lb] = pb[kk].z; Bs[kc+3][lb] = pb[kk].w;
        }
        __syncthreads();
        k0 += 32;
        if (k0 < K){
#pragma unroll
            for (int kk = 0; kk < 2; kk++) pa[kk] = *(const float4*)(Ag + k0 + kk * 16);
#pragma unroll
            for (int kk = 0; kk < 4; kk++) pb[kk] = *(const float4*)(Bg + k0 + kk * 8);
        }
#pragma unroll
        for (int kk = 0; kk < 32; kk++){
            float4 a0 = *(const float4*)&As[kk][ty * 4];
            ulonglong2 b0 = *(const ulonglong2*)&Bs[kk][tx * 4];
            ulonglong2 b1 = *(const ulonglong2*)&Bs[kk][64 + tx * 4];
            unsigned long long bv[4] = {b0.x, b0.y, b1.x, b1.y};
            float avf[4] = {a0.x, a0.y, a0.z, a0.w};
            unsigned long long av[4];
#pragma unroll
            for (int i = 0; i < 4; i++) av[i] = packdup(avf[i]);
#pragma unroll
            for (int i = 0; i < 4; i++)
#pragma unroll
                for (int j = 0; j < 4; j++)
                    fma2(acc2[i][j], av[i], bv[j]);
        }
        if (k0 >= K) break;
    }

    float acc[4][8];
#pragma unroll
    for (int i = 0; i < 4; i++)
#pragma unroll
        for (int j = 0; j < 4; j++)
            unpack2(acc2[i][j], acc[i][2*j], acc[i][2*j+1]);

    float bvals[8];
#pragma unroll
    for (int jj = 0; jj < 2; jj++){
        int c = n0 + jj * 64 + tx * 4;
        if (bias){
            float4 bb = *(const float4*)(bias + c);
            bvals[jj*4+0] = bb.x * bscale; bvals[jj*4+1] = bb.y * bscale;
            bvals[jj*4+2] = bb.z * bscale; bvals[jj*4+3] = bb.w * bscale;
        } else {
            bvals[jj*4+0] = bvals[jj*4+1] = bvals[jj*4+2] = bvals[jj*4+3] = 0.f;
        }
    }
#pragma unroll
    for (int ii = 0; ii < 4; ii++){
        int r = m0 + ty * 4 + ii;
#pragma unroll
        for (int jj = 0; jj < 2; jj++){
            int c = n0 + jj * 64 + tx * 4;
            float4 v;
            v.x = fmaf(acc[ii][jj*4+0], alpha, bvals[jj*4+0]);
            v.y = fmaf(acc[ii][jj*4+1], alpha, bvals[jj*4+1]);
            v.z = fmaf(acc[ii][jj*4+2], alpha, bvals[jj*4+2]);
            v.w = fmaf(acc[ii][jj*4+3], alpha, bvals[jj*4+3]);
            if (mode == 0){
                *(float4*)(C + (size_t)r * N + c) = v;
            } else if (mode == 1){
                int b = r >> 11, s = r & 2047;
                int h = c >> 6,  hd = c & 63;
                *(float4*)(C + (((size_t)(b * NHEAD + h) * SEQ + s) << 6) + hd) = v;
            } else {
                int b = r >> 11, s = r & 2047;
                int h = c >> 6,  hd = c & 63;
                size_t base = (((size_t)(b * NHEAD + h) * SEQ + s) << 6) + hd;
                if (b < 2){
                    float vv[4] = {v.x, v.y, v.z, v.w};
                    __nv_bfloat16 hi[4], mi[4], lo[4];
#pragma unroll
                    for (int j = 0; j < 4; j++){
                        float f = vv[j];
                        hi[j] = __float2bfloat16(f);
                        float r1 = f - __bfloat162float(hi[j]);
                        mi[j] = __float2bfloat16(r1);
                        float r2 = r1 - __bfloat162float(mi[j]);
                        lo[j] = __float2bfloat16(r2);
                    }
                    *(__nv_bfloat162*)(o1 + base)     = __nv_bfloat162(hi[0], hi[1]);
                    *(__nv_bfloat162*)(o1 + base + 2) = __nv_bfloat162(hi[2], hi[3]);
                    *(__nv_bfloat162*)(o2 + base)     = __nv_bfloat162(mi[0], mi[1]);
                    *(__nv_bfloat162*)(o2 + base + 2) = __nv_bfloat162(mi[2], mi[3]);
                    *(__nv_bfloat162*)(o3 + base)     = __nv_bfloat162(lo[0], lo[1]);
                    *(__nv_bfloat162*)(o3 + base + 2) = __nv_bfloat162(lo[2], lo[3]);
                } else {
                    *(float4*)(C + base) = v;
                }
            }
        }
    }
}

__global__ void __launch_bounds__(256) qkv_kernel(
    const float* __restrict__ x,
    const float* __restrict__ Wq, const float* __restrict__ bq,
    const float* __restrict__ Wk, const float* __restrict__ bk,
    const float* __restrict__ Wv, const float* __restrict__ bv,
    __nv_bfloat16* Qh, __nv_bfloat16* Qm, __nv_bfloat16* Ql,
    __nv_bfloat16* Kh, __nv_bfloat16* Km, __nv_bfloat16* Kl,
    float* Qf, float* Kf, float* Vp)
{
    int z = blockIdx.z;
    int m0 = blockIdx.y * 64, n0 = blockIdx.x * 128;
    if (z == 0){
        gemm_tile64(x, Wq, bq, Qf, DIM, DIM, 0.125f, 0.125f, m0, n0, 2, Qh, Qm, Ql);
    } else if (z == 1){
        gemm_tile64(x, Wk, bk, Kf, DIM, DIM, 1.f, 1.f, m0, n0, 2, Kh, Km, Kl);
    } else {
        gemm_tile64(x, Wv, bv, Vp, DIM, DIM, 1.f, 1.f, m0, n0, 1, nullptr, nullptr, nullptr);
    }
}

__global__ void __launch_bounds__(256) gemm_kernel(
    const float* __restrict__ A, const float* __restrict__ B,
    const float* __restrict__ bias, float* __restrict__ C,
    int K, int N, float alpha)
{
    gemm_tile64(A, B, bias, C, K, N, alpha, 1.f, blockIdx.y * 64, blockIdx.x * 128, 0,
                nullptr, nullptr, nullptr);
}

// =====================================================================
// stage-1 mean over seq; gate kernel finishes the mean + computes gproj
// =====================================================================
__global__ void mean1_kernel(const float* __restrict__ x, float* __restrict__ part)
{
    int b = blockIdx.x, c = blockIdx.y, t = threadIdx.x;
    const float* p = x + ((size_t)b * SEQ + c * 128) * DIM + t;
    float s = 0.f;
    for (int i = 0; i < 128; i++) s += p[(size_t)i * DIM];
    part[(b * 16 + c) * DIM + t] = s;
}

__global__ void gate_kernel(const float* __restrict__ part,
    const float* __restrict__ Wg, const float* __restrict__ bg,
    const float* __restrict__ Wgp, const float* __restrict__ bgp,
    float* __restrict__ gproj)
{
    __shared__ float xm[BATCH * DIM];
    __shared__ float gg[BATCH][16];
    int t = threadIdx.x;
    for (int idx = t; idx < BATCH * DIM; idx += 256){
        int b = idx >> 8, d = idx & 255;
        float s = 0.f;
#pragma unroll
        for (int i = 0; i < 16; i++) s += part[(b * 16 + i) * DIM + d];
        xm[idx] = s * (1.0f / SEQ);
    }
    __syncthreads();
    if (t < BATCH * 16){
        int b = t >> 4, j = t & 15;
        const float* x0 = xm + b * DIM;
        const float* w  = Wg + j * DIM;
        float s = bg[j];
        for (int d = 0; d < DIM; d++) s = fmaf(x0[d], w[d], s);
        gg[b][j] = 1.f / (1.f + expf(-s));
    }
    __syncthreads();
    for (int idx = t; idx < BATCH * DIM; idx += 256){
        int b = idx >> 8, d = idx & 255;
        const float* w = Wgp + d * 16;
        float s = bgp[d];
#pragma unroll
        for (int j = 0; j < 16; j++) s = fmaf(gg[b][j], w[j], s);
        gproj[idx] = s;
    }
}

// =====================================================================
// per-row: quantile threshold -> masked softmax -> sparse att = p @ V
//          -> fused distill+gate mix (head-local, 16-wide groups).
// =====================================================================
__global__ void __launch_bounds__(256) attn_row_kernel(
    const float* __restrict__ scores,
    const float* __restrict__ V,
    const float* __restrict__ Wd, const float* __restrict__ bd,
    const float* __restrict__ gproj,
    float* __restrict__ mixed)
{
    __shared__ float pv[SEQ];
    __shared__ unsigned short idxs[SEQ];
    __shared__ int hist[256];
    __shared__ int wsum[8];
    __shared__ float fred[8];
    __shared__ float accbuf[8][64];
    __shared__ float arow[64];
    __shared__ int s_bin, s_rem;
    __shared__ float s_slo, s_max, s_sum;

    const int t = threadIdx.x, lane = t & 31, w = t >> 5;
    const int r = NROWS - 1 - blockIdx.x;
    const int q = r & (SEQ - 1), bh = r >> 11;

    const float4* row4 = (const float4*)(scores + (size_t)r * SEQ);
    float4 f0 = row4[t], f1 = row4[256 + t];
    float sv[8] = {f0.x, f0.y, f0.z, f0.w, f1.x, f1.y, f1.z, f1.w};
    unsigned kv[8];
#pragma unroll
    for (int i = 0; i < 8; i++) kv[i] = f2k(sv[i]);

    float lmax = sv[0];
#pragma unroll
    for (int i = 1; i < 8; i++) lmax = fmaxf(lmax, sv[i]);
#pragma unroll
    for (int o = 16; o; o >>= 1)
        lmax = fmaxf(lmax, __shfl_xor_sync(0xffffffffu, lmax, o));
    if (lane == 0) fred[w] = lmax;
    __syncthreads();
    if (t == 0){
        float m = fred[0];
#pragma unroll
        for (int i = 1; i < 8; i++) m = fmaxf(m, fred[i]);
        s_max = m;
    }

    // ---- radix select: value of rank-205 (205th largest) ----
    unsigned prefix = 0;
    int rem = 205;
#pragma unroll
    for (int shift = 24; shift >= 0; shift -= 8){
        hist[t] = 0;
        __syncthreads();
        unsigned himask = (shift == 24) ? 0u : (0xFFFFFFFFu << (shift + 8));
#pragma unroll
        for (int i = 0; i < 8; i++){
            if ((kv[i] & himask) == prefix)
                atomicAdd(&hist[(kv[i] >> shift) & 0xFFu], 1);
        }
        __syncthreads();
        int u = 255 - t;
        int s = hist[u];
#pragma unroll
        for (int o = 1; o < 32; o <<= 1){
            int n = __shfl_up_sync(0xffffffffu, s, o);
            if (lane >= o) s += n;
        }
        if (lane == 31) wsum[w] = s;
        __syncthreads();
        int off = 0;
#pragma unroll
        for (int i = 0; i < 8; i++) if (i < w) off += wsum[i];
        int pprev = __shfl_up_sync(0xffffffffu, s, 1);
        int nxt = (lane > 0) ? (off + pprev) : off;
        int sfx = off + s;
        if (sfx >= rem && nxt < rem){ s_bin = u; s_rem = rem - nxt; }
        __syncthreads();
        prefix |= ((unsigned)s_bin) << shift;
        rem = s_rem;
    }
    float shi = k2f(prefix);

    // ---- rank-206: count >= shi; max < shi ----
    int cge = 0;
    float lmlt = -3.4e38f;
#pragma unroll
    for (int i = 0; i < 8; i++){
        if (sv[i] >= shi) cge++;
        else lmlt = fmaxf(lmlt, sv[i]);
    }
#pragma unroll
    for (int o = 16; o; o >>= 1){
        cge  += __shfl_xor_sync(0xffffffffu, cge, o);
        lmlt  = fmaxf(lmlt, __shfl_xor_sync(0xffffffffu, lmlt, o));
    }
    if (lane == 0){ hist[w] = cge; fred[w] = lmlt; }
    __syncthreads();
    if (t == 0){
        int c = 0; float m = -3.4e38f;
#pragma unroll
        for (int i = 0; i < 8; i++){ c += hist[i]; m = fmaxf(m, fred[i]); }
        s_slo = (c >= 206) ? shi : m;
    }
    __syncthreads();
    float slo = s_slo;
    const float idxf = 0.9f * 2047.0f;
    const float frac = idxf - 1842.0f;
    float thr = slo + frac * (shi - slo);
    float rowmax = s_max;

    // ---- exp + deterministic compaction ----
    float ev[8];
    unsigned kmask = 0;
    int kcnt = 0;
    float lsum = 0.f;
#pragma unroll
    for (int i = 0; i < 8; i++){
        ev[i] = 0.f;
        if (sv[i] >= thr){
            float e = expf(sv[i] - rowmax);
            ev[i] = e; lsum += e;
            kmask |= (1u << i); kcnt++;
        }
    }
    int ps = kcnt;
#pragma unroll
    for (int o = 1; o < 32; o <<= 1){
        int n = __shfl_up_sync(0xffffffffu, ps, o);
        if (lane >= o) ps += n;
    }
    if (lane == 31) wsum[w] = ps;
#pragma unroll
    for (int o = 16; o; o >>= 1)
        lsum += __shfl_xor_sync(0xffffffffu, lsum, o);
    if (lane == 0) fred[w] = lsum;
    __syncthreads();
    int off = 0, tot = 0;
#pragma unroll
    for (int i = 0; i < 8; i++){ if (i < w) off += wsum[i]; tot += wsum[i]; }
    int pos = off + ps - kcnt;
#pragma unroll
    for (int i = 0; i < 8; i++){
        if (kmask & (1u << i)){
            idxs[pos] = (unsigned short)((i < 4) ? (4 * t + i) : (1024 + 4 * t + i - 4));
            pv[pos] = ev[i];
            pos++;
        }
    }
    if (t == 0){
        float ss = 0.f;
#pragma unroll
        for (int i = 0; i < 8; i++) ss += fred[i];
        s_sum = ss;
    }
    __syncthreads();

    // ---- sparse att: 8 warps, float2 per lane, 8-way unrolled gather ----
    const float inv = 1.0f / s_sum;
    const float2* Vh2 = (const float2*)(V + (size_t)bh * SEQ * HDIM);
    float a0 = 0.f, a1 = 0.f, a2 = 0.f, a3 = 0.f;
    float a4 = 0.f, a5 = 0.f, a6 = 0.f, a7 = 0.f;
    int j = w;
    for (; j + 56 < tot; j += 64){
        float p[8];
        unsigned ix[8];
#pragma unroll
        for (int u = 0; u < 8; u++){
            p[u]  = pv[j + 8 * u];
            ix[u] = idxs[j + 8 * u];
        }
        float2 v[8];
#pragma unroll
        for (int u = 0; u < 8; u++)
            v[u] = Vh2[ix[u] * 32 + lane];
        a0 += p[0] * v[0].x; a1 += p[0] * v[0].y;
        a2 += p[1] * v[1].x; a3 += p[1] * v[1].y;
        a4 += p[2] * v[2].x; a5 += p[2] * v[2].y;
        a6 += p[3] * v[3].x; a7 += p[3] * v[3].y;
        a0 += p[4] * v[4].x; a1 += p[4] * v[4].y;
        a2 += p[5] * v[5].x; a3 += p[5] * v[5].y;
        a4 += p[6] * v[6].x; a5 += p[6] * v[6].y;
        a6 += p[7] * v[7].x; a7 += p[7] * v[7].y;
    }
    for (; j < tot; j += 8){
        float pp = pv[j];
        float2 vr = Vh2[(unsigned)idxs[j] * 32 + lane];
        a0 += pp * vr.x;
        a1 += pp * vr.y;
    }
    a0 += a2 + a4 + a6;
    a1 += a3 + a5 + a7;
    accbuf[w][2 * lane]     = a0;
    accbuf[w][2 * lane + 1] = a1;
    __syncthreads();
    if (t < 64){
        float tt = 0.f;
#pragma unroll
        for (int w2 = 0; w2 < 8; w2++) tt += accbuf[w2][t];
        arow[t] = tt * inv;
    }
    __syncthreads();

    // ---- fused distill + gate mix (16-wide groups are head-local) ----
    if (t < 64){
        const int h = bh & (NHEAD - 1), b = bh >> 2;
        const int g16 = (t >> 4) << 4;
        const int jrow = t & 15;
        float s = bd[jrow];
#pragma unroll
        for (int j2 = 0; j2 < 16; j2++)
            s = fmaf(arow[g16 + j2], Wd[jrow * 16 + j2], s);
        float av = arow[t];
        float g = gproj[b * DIM + h * HDIM + t];
        mixed[((size_t)b * SEQ + q) * DIM + h * HDIM + t] = g * s + (1.f - g) * av;
    }
}

// ---- persistent side stream + events (created on first, uncaptured call) ----
static cudaStream_t g_side = nullptr;
static cudaEvent_t g_ev[2];
static int g_ok = 0;

// =====================================================================
extern "C" void kernel_launch(void* const* d_in, const int* in_sizes, int n_in,
                              void* d_out, int out_size)
{
    (void)in_sizes; (void)n_in; (void)out_size;
    const float* x   = (const float*)d_in[0];
    const float* Wq  = (const float*)d_in[1];
    const float* bq  = (const float*)d_in[2];
    const float* Wk  = (const float*)d_in[3];
    const float* bk  = (const float*)d_in[4];
    const float* Wv  = (const float*)d_in[5];
    const float* bv  = (const float*)d_in[6];
    const float* Wd  = (const float*)d_in[7];
    const float* bd  = (const float*)d_in[8];
    const float* Wg  = (const float*)d_in[9];
    const float* bg  = (const float*)d_in[10];
    const float* Wgp = (const float*)d_in[11];
    const float* bgp = (const float*)d_in[12];
    const float* Wo  = (const float*)d_in[13];
    const float* bo  = (const float*)d_in[14];
    float* out = (float*)d_out;

    __nv_bfloat16 *pQh, *pQm, *pQl, *pKh, *pKm, *pKl;
    float *pQf, *pKf, *pV, *pS, *pMix, *pGp, *pMp;
    cudaGetSymbolAddress((void**)&pQh, g_Qh);
    cudaGetSymbolAddress((void**)&pQm, g_Qm);
    cudaGetSymbolAddress((void**)&pQl, g_Ql);
    cudaGetSymbolAddress((void**)&pKh, g_Kh);
    cudaGetSymbolAddress((void**)&pKm, g_Km);
    cudaGetSymbolAddress((void**)&pKl, g_Kl);
    cudaGetSymbolAddress((void**)&pQf, g_Qf);
    cudaGetSymbolAddress((void**)&pKf, g_Kf);
    cudaGetSymbolAddress((void**)&pV,   g_V);
    cudaGetSymbolAddress((void**)&pS,   g_scores);
    cudaGetSymbolAddress((void**)&pMix, g_mixed);
    cudaGetSymbolAddress((void**)&pGp,  g_gproj);
    cudaGetSymbolAddress((void**)&pMp,  g_mpart);

    cudaFuncSetAttribute(scores_hybrid_kernel,
                         cudaFuncAttributeMaxDynamicSharedMemorySize, SMMA_SMEM);

    // one-time side-stream/event setup (runs on the uncaptured correctness call)
    cudaStreamCaptureStatus cap = cudaStreamCaptureStatusNone;
    cudaStreamIsCapturing((cudaStream_t)0, &cap);
    if (!g_side && cap == cudaStreamCaptureStatusNone){
        int ok = 1;
        if (cudaStreamCreateWithFlags(&g_side, cudaStreamNonBlocking) != cudaSuccess) ok = 0;
        for (int i = 0; ok && i < 2; i++)
            if (cudaEventCreateWithFlags(&g_ev[i], cudaEventDisableTiming) != cudaSuccess) ok = 0;
        g_ok = ok;
        if (!ok) g_side = nullptr;
    }
    const int overlap = (g_ok && g_side);

    if (overlap){
        // fork: gate path (tiny) runs on side stream, overlapped with qkv
        cudaEventRecord(g_ev[0], (cudaStream_t)0);
        cudaStreamWaitEvent(g_side, g_ev[0], 0);
        mean1_kernel<<<dim3(BATCH, 16), 256, 0, g_side>>>(x, pMp);
        gate_kernel<<<1, 256, 0, g_side>>>(pMp, Wg, bg, Wgp, bgp, pGp);
        cudaEventRecord(g_ev[1], g_side);
    } else {
        mean1_kernel<<<dim3(BATCH, 16), 256>>>(x, pMp);
        gate_kernel<<<1, 256>>>(pMp, Wg, bg, Wgp, bgp, pGp);
    }

    qkv_kernel<<<dim3(DIM / 128, (BATCH * SEQ) / 64, 3), 256>>>(
        x, Wq, bq, Wk, bk, Wv, bv, pQh, pQm, pQl, pKh, pKm, pKl, pQf, pKf, pV);

    scores_hybrid_kernel<<<dim3(32, 16, 8), 256, SMMA_SMEM>>>(
        pQh, pQm, pQl, pKh, pKm, pKl, pQf, pKf, pS);

    if (overlap) cudaStreamWaitEvent((cudaStream_t)0, g_ev[1], 0);   // join gate
    attn_row_kernel<<<NROWS, 256>>>(pS, pV, Wd, bd, pGp, pMix);

    gemm_kernel<<<dim3(DIM / 128, (BATCH * SEQ) / 64, 1), 256>>>(
        pMix, Wo, bo, out, DIM, DIM, 1.f);
}

// round 16
// speedup vs baseline: 1.0770x; 1.0770x over previous
#include <cuda_runtime.h>
#include <cuda_bf16.h>
#include <math.h>
#include <stdint.h>

#define BATCH 4
#define SEQ   2048
#define DIM   256
#define NHEAD 4
#define HDIM  64
#define NROWS (BATCH*NHEAD*SEQ)

// ---- scratch (allocation-free: device globals) ----
static __device__ __nv_bfloat16 g_Qh[BATCH*NHEAD*SEQ*HDIM];
static __device__ __nv_bfloat16 g_Qm[BATCH*NHEAD*SEQ*HDIM];
static __device__ __nv_bfloat16 g_Ql[BATCH*NHEAD*SEQ*HDIM];
static __device__ __nv_bfloat16 g_Kh[BATCH*NHEAD*SEQ*HDIM];
static __device__ __nv_bfloat16 g_Km[BATCH*NHEAD*SEQ*HDIM];
static __device__ __nv_bfloat16 g_Kl[BATCH*NHEAD*SEQ*HDIM];
static __device__ float g_Qf[BATCH*NHEAD*SEQ*HDIM];   // fp32 (scaled) for FMA heads
static __device__ float g_Kf[BATCH*NHEAD*SEQ*HDIM];
static __device__ float g_V[BATCH*NHEAD*SEQ*HDIM];
static __device__ float g_scores[(size_t)NROWS * SEQ];   // 268 MB
static __device__ float g_mixed[BATCH*SEQ*DIM];
static __device__ float g_gproj[BATCH*DIM];
static __device__ float g_mpart[BATCH*16*DIM];

// ---- order-preserving float<->uint key transform ----
__device__ __forceinline__ unsigned f2k(float f){
    unsigned u = __float_as_uint(f);
    return (u & 0x80000000u) ? ~u : (u | 0x80000000u);
}
__device__ __forceinline__ float k2f(unsigned k){
    return (k & 0x80000000u) ? __uint_as_float(k & 0x7fffffffu)
                             : __uint_as_float(~k);
}

// ---- packed f32x2 FMA helpers (PTX >= 8.6, sm_100 family) ----
__device__ __forceinline__ unsigned long long packdup(float x){
    unsigned long long r;
    unsigned u = __float_as_uint(x);
    asm("mov.b64 %0, {%1, %1};" : "=l"(r) : "r"(u));
    return r;
}
__device__ __forceinline__ void fma2(unsigned long long &c,
                                     unsigned long long a, unsigned long long b){
    asm("fma.rn.f32x2 %0, %1, %2, %0;" : "+l"(c) : "l"(a), "l"(b));
}
__device__ __forceinline__ void unpack2(unsigned long long v, float &x, float &y){
    unsigned lo, hi;
    asm("mov.b64 {%0, %1}, %2;" : "=r"(lo), "=r"(hi) : "l"(v));
    x = __uint_as_float(lo);
    y = __uint_as_float(hi);
}

// ---- mma.sync helpers (baseline PTX, valid on compute_103) ----
__device__ __forceinline__ uint32_t smem_u32(const void* p){
    uint32_t a;
    asm("{ .reg .u64 t; cvta.to.shared.u64 t, %1; cvt.u32.u64 %0, t; }"
        : "=r"(a) : "l"(p));
    return a;
}
#define SW128(o) ((o) ^ (((o) >> 3) & 0x70))

__device__ __forceinline__ void ldsm_x4(uint32_t addr, uint32_t* r){
    asm volatile("ldmatrix.sync.aligned.m8n8.x4.shared.b16 {%0,%1,%2,%3}, [%4];"
        : "=r"(r[0]), "=r"(r[1]), "=r"(r[2]), "=r"(r[3]) : "r"(addr));
}
__device__ __forceinline__ void ldsm_x2(uint32_t addr, uint32_t* r){
    asm volatile("ldmatrix.sync.aligned.m8n8.x2.shared.b16 {%0,%1}, [%2];"
        : "=r"(r[0]), "=r"(r[1]) : "r"(addr));
}
__device__ __forceinline__ void mma16816(float* c, const uint32_t* a, const uint32_t* b){
    asm volatile("mma.sync.aligned.m16n8k16.row.col.f32.bf16.bf16.f32 "
        "{%0,%1,%2,%3}, {%4,%5,%6,%7}, {%8,%9}, {%0,%1,%2,%3};"
        : "+f"(c[0]), "+f"(c[1]), "+f"(c[2]), "+f"(c[3])
        : "r"(a[0]), "r"(a[1]), "r"(a[2]), "r"(a[3]), "r"(b[0]), "r"(b[1]));
}

#define STILE 16384
#define SMMA_SMEM (6*STILE)

// =====================================================================
// HMMA path: one 128x128 score tile via 6-pass triple-bf16-split.
// =====================================================================
__device__ void hmma_scores_tile(char* smem,
    const __nv_bfloat16* __restrict__ Qh, const __nv_bfloat16* __restrict__ Qm,
    const __nv_bfloat16* __restrict__ Ql, const __nv_bfloat16* __restrict__ Kh,
    const __nv_bfloat16* __restrict__ Km, const __nv_bfloat16* __restrict__ Kl,
    float* __restrict__ S, int bh, int m0, int n0)
{
    const int t = threadIdx.x, lane = t & 31, wid = t >> 5;

    const __nv_bfloat16* srcs[6] = {Qh, Qm, Ql, Kh, Km, Kl};
    const int row = t >> 1, half = t & 1;
#pragma unroll
    for (int p = 0; p < 6; p++){
        int br = (p < 3) ? m0 : n0;
        const uint4* src = (const uint4*)(srcs[p] + (((size_t)bh * SEQ) + br + row) * HDIM) + half * 4;
        char* tile = smem + p * STILE;
#pragma unroll
        for (int j = 0; j < 4; j++){
            uint4 v = src[j];
            uint32_t off = row * 128 + (half * 4 + j) * 16;
            *(uint4*)(tile + SW128(off)) = v;
        }
    }
    __syncthreads();

    const uint32_t smem_b = smem_u32(smem);
    const int wm = wid >> 2, wn = wid & 3;

    float acc[4][4][4];
#pragma unroll
    for (int i = 0; i < 4; i++)
#pragma unroll
        for (int j = 0; j < 4; j++)
#pragma unroll
            for (int k = 0; k < 4; k++) acc[i][j][k] = 0.f;

    const int a_t = lane >> 3, a_r = lane & 7;
    const int a_rowoff = (a_t & 1) * 8 + a_r;
    const int a_coloff = (a_t >> 1) * 16;
    const int b_r = lane & 7;
    const int b_coloff = ((lane >> 3) & 1) * 16;

    const int nb[3] = {3, 2, 1};
#pragma unroll
    for (int ai = 0; ai < 3; ai++){
        const uint32_t abase = smem_b + ai * STILE;
#pragma unroll
        for (int ks = 0; ks < 4; ks++){
            const int kb = ks * 32;
            uint32_t a[4][4];
#pragma unroll
            for (int mi = 0; mi < 4; mi++){
                uint32_t off = (uint32_t)(wm * 64 + mi * 16 + a_rowoff) * 128 + kb + a_coloff;
                ldsm_x4(abase + SW128(off), a[mi]);
            }
#pragma unroll
            for (int bi = 0; bi < 3; bi++){
                if (bi >= nb[ai]) break;
                const uint32_t bbase = smem_b + (3 + bi) * STILE;
                uint32_t b[4][2];
#pragma unroll
                for (int nj = 0; nj < 4; nj++){
                    uint32_t off = (uint32_t)(wn * 32 + nj * 8 + b_r) * 128 + kb + b_coloff;
                    ldsm_x2(bbase + SW128(off), b[nj]);
                }
#pragma unroll
                for (int mi = 0; mi < 4; mi++)
#pragma unroll
                    for (int nj = 0; nj < 4; nj++)
                        mma16816(acc[mi][nj], a[mi], b[nj]);
            }
        }
    }

    const int gid = lane >> 2, tig = lane & 3;
    float* Sb = S + (size_t)bh * SEQ * SEQ;
#pragma unroll
    for (int mi = 0; mi < 4; mi++){
        int r0 = m0 + wm * 64 + mi * 16 + gid;
#pragma unroll
        for (int nj = 0; nj < 4; nj++){
            int c = n0 + wn * 32 + nj * 8 + 2 * tig;
            float2 v0 = make_float2(acc[mi][nj][0], acc[mi][nj][1]);
            float2 v1 = make_float2(acc[mi][nj][2], acc[mi][nj][3]);
            *(float2*)(Sb + (size_t)r0 * SEQ + c)       = v0;
            *(float2*)(Sb + (size_t)(r0 + 8) * SEQ + c) = v1;
        }
    }
}

// =====================================================================
// FMA path: one 128x128 score tile, fp32 via packed f32x2 FMA.
// =====================================================================
__device__ void fma_scores_tile(char* smem_raw,
    const float* __restrict__ Qf, const float* __restrict__ Kf,
    float* __restrict__ S, int bh, int m0, int n0)
{
    float (*As)[132] = reinterpret_cast<float(*)[132]>(smem_raw);
    float (*Bs)[132] = reinterpret_cast<float(*)[132]>(smem_raw + 32 * 132 * sizeof(float));
    const float* A = Qf + (size_t)bh * SEQ * HDIM;
    const float* B = Kf + (size_t)bh * SEQ * HDIM;
    const int tid = threadIdx.x;
    const int tx = tid & 15, ty = tid >> 4;
    const int lm = tid >> 1, lk4 = tid & 1;

    const float* Ag = A + (size_t)(m0 + lm) * HDIM + lk4 * 4;
    const float* Bg = B + (size_t)(n0 + lm) * HDIM + lk4 * 4;

    unsigned long long acc2[8][4];
#pragma unroll
    for (int i = 0; i < 8; i++)
#pragma unroll
        for (int j = 0; j < 4; j++) acc2[i][j] = 0ull;

#pragma unroll
    for (int it = 0; it < 2; it++){
        int k0 = it * 32;
        float4 pa[4], pb[4];
#pragma unroll
        for (int kk = 0; kk < 4; kk++){
            pa[kk] = *(const float4*)(Ag + k0 + kk * 8);
            pb[kk] = *(const float4*)(Bg + k0 + kk * 8);
        }
        __syncthreads();
#pragma unroll
        for (int kk = 0; kk < 4; kk++){
            int kc = lk4 * 4 + kk * 8;
            As[kc+0][lm] = pa[kk].x; As[kc+1][lm] = pa[kk].y;
            As[kc+2][lm] = pa[kk].z; As[kc+3][lm] = pa[kk].w;
            Bs[kc+0][lm] = pb[kk].x; Bs[kc+1][lm] = pb[kk].y;
            Bs[kc+2][lm] = pb[kk].z; Bs[kc+3][lm] = pb[kk].w;
        }
        __syncthreads();
#pragma unroll
        for (int kk = 0; kk < 32; kk++){
            float4 a0 = *(const float4*)&As[kk][ty * 4];
            float4 a1 = *(const float4*)&As[kk][64 + ty * 4];
            ulonglong2 b0 = *(const ulonglong2*)&Bs[kk][tx * 4];
            ulonglong2 b1 = *(const ulonglong2*)&Bs[kk][64 + tx * 4];
            unsigned long long bv[4] = {b0.x, b0.y, b1.x, b1.y};
            float avf[8] = {a0.x, a0.y, a0.z, a0.w, a1.x, a1.y, a1.z, a1.w};
            unsigned long long av[8];
#pragma unroll
            for (int i = 0; i < 8; i++) av[i] = packdup(avf[i]);
#pragma unroll
            for (int i = 0; i < 8; i++)
#pragma unroll
                for (int j = 0; j < 4; j++)
                    fma2(acc2[i][j], av[i], bv[j]);
        }
    }

    float* Sb = S + (size_t)bh * SEQ * SEQ;
#pragma unroll
    for (int ii = 0; ii < 8; ii++){
        int r = m0 + ((ii < 4) ? (ty * 4 + ii) : (64 + ty * 4 + ii - 4));
#pragma unroll
        for (int jj = 0; jj < 2; jj++){
            int c = n0 + jj * 64 + tx * 4;
            float4 v;
            unpack2(acc2[ii][jj*2+0], v.x, v.y);
            unpack2(acc2[ii][jj*2+1], v.z, v.w);
            *(float4*)(Sb + (size_t)r * SEQ + c) = v;
        }
    }
}

// =====================================================================
// Hybrid scores kernel: even blockIdx.x -> HMMA (heads 0-7),
// odd -> fp32 FMA (heads 8-15). Monolithic launch (full waves).
// =====================================================================
__global__ void __launch_bounds__(256, 2) scores_hybrid_kernel(
    const __nv_bfloat16* __restrict__ Qh, const __nv_bfloat16* __restrict__ Qm,
    const __nv_bfloat16* __restrict__ Ql, const __nv_bfloat16* __restrict__ Kh,
    const __nv_bfloat16* __restrict__ Km, const __nv_bfloat16* __restrict__ Kl,
    const float* __restrict__ Qf, const float* __restrict__ Kf,
    float* __restrict__ S)
{
    extern __shared__ char smem[];
    const int type = blockIdx.x & 1;
    const int n0 = (blockIdx.x >> 1) * 128;
    const int m0 = blockIdx.y * 128;
    if (type == 0){
        hmma_scores_tile(smem, Qh, Qm, Ql, Kh, Km, Kl, S, blockIdx.z, m0, n0);
    } else {
        fma_scores_tile(smem, Qf, Kf, S, 8 + blockIdx.z, m0, n0);
    }
}

// =====================================================================
// 128x128 SGEMM tile body (static smem, f32x2 inner loop): modes:
//  0: fp32 row-major; 1: fp32 scatter [b,h,s,hd];
//  2: QK epilogue — batches 0,1 -> bf16 triple-split, batches 2,3 -> fp32 (C)
// =====================================================================
__device__ __forceinline__ void gemm_tile(
    const float* __restrict__ A, const float* __restrict__ B,
    const float* __restrict__ bias, float* __restrict__ C,
    int K, int N, float alpha, float bscale, int m0, int n0, int mode,
    __nv_bfloat16* __restrict__ o1, __nv_bfloat16* __restrict__ o2,
    __nv_bfloat16* __restrict__ o3)
{
    __shared__ float As[32][132];
    __shared__ float Bs[32][132];
    const int tid = threadIdx.x;
    const int tx = tid & 15, ty = tid >> 4;
    const int lm = tid >> 1;
    const int lk4 = tid & 1;

    const float* Ag = A + (size_t)(m0 + lm) * K + lk4 * 4;
    const float* Bg = B + (size_t)(n0 + lm) * K + lk4 * 4;

    float4 pa[4], pb[4];
#pragma unroll
    for (int kk = 0; kk < 4; kk++){
        pa[kk] = *(const float4*)(Ag + kk * 8);
        pb[kk] = *(const float4*)(Bg + kk * 8);
    }

    unsigned long long acc2[8][4];
#pragma unroll
    for (int i = 0; i < 8; i++)
#pragma unroll
        for (int j = 0; j < 4; j++) acc2[i][j] = 0ull;

    int k0 = 0;
    for (;;){
        __syncthreads();
#pragma unroll
        for (int kk = 0; kk < 4; kk++){
            int kc = lk4 * 4 + kk * 8;
            As[kc+0][lm] = pa[kk].x; As[kc+1][lm] = pa[kk].y;
            As[kc+2][lm] = pa[kk].z; As[kc+3][lm] = pa[kk].w;
            Bs[kc+0][lm] = pb[kk].x; Bs[kc+1][lm] = pb[kk].y;
            Bs[kc+2][lm] = pb[kk].z; Bs[kc+3][lm] = pb[kk].w;
        }
        __syncthreads();
        k0 += 32;
        if (k0 < K){
#pragma unroll
            for (int kk = 0; kk < 4; kk++){
                pa[kk] = *(const float4*)(Ag + k0 + kk * 8);
                pb[kk] = *(const float4*)(Bg + k0 + kk * 8);
            }
        }
#pragma unroll
        for (int kk = 0; kk < 32; kk++){
            float4 a0 = *(const float4*)&As[kk][ty * 4];
            float4 a1 = *(const float4*)&As[kk][64 + ty * 4];
            ulonglong2 b0 = *(const ulonglong2*)&Bs[kk][tx * 4];
            ulonglong2 b1 = *(const ulonglong2*)&Bs[kk][64 + tx * 4];
            unsigned long long bv[4] = {b0.x, b0.y, b1.x, b1.y};
            float avf[8] = {a0.x, a0.y, a0.z, a0.w, a1.x, a1.y, a1.z, a1.w};
            unsigned long long av[8];
#pragma unroll
            for (int i = 0; i < 8; i++) av[i] = packdup(avf[i]);
#pragma unroll
            for (int i = 0; i < 8; i++)
#pragma unroll
                for (int j = 0; j < 4; j++)
                    fma2(acc2[i][j], av[i], bv[j]);
        }
        if (k0 >= K) break;
    }

    float acc[8][8];
#pragma unroll
    for (int i = 0; i < 8; i++)
#pragma unroll
        for (int j = 0; j < 4; j++)
            unpack2(acc2[i][j], acc[i][2*j], acc[i][2*j+1]);

    float bvals[8];
#pragma unroll
    for (int jj = 0; jj < 2; jj++){
        int c = n0 + jj * 64 + tx * 4;
        if (bias){
            float4 bb = *(const float4*)(bias + c);
            bvals[jj*4+0] = bb.x * bscale; bvals[jj*4+1] = bb.y * bscale;
            bvals[jj*4+2] = bb.z * bscale; bvals[jj*4+3] = bb.w * bscale;
        } else {
            bvals[jj*4+0] = bvals[jj*4+1] = bvals[jj*4+2] = bvals[jj*4+3] = 0.f;
        }
    }
#pragma unroll
    for (int ii = 0; ii < 8; ii++){
        int r = m0 + ((ii < 4) ? (ty * 4 + ii) : (64 + ty * 4 + ii - 4));
#pragma unroll
        for (int jj = 0; jj < 2; jj++){
            int c = n0 + jj * 64 + tx * 4;
            float4 v;
            v.x = fmaf(acc[ii][jj*4+0], alpha, bvals[jj*4+0]);
            v.y = fmaf(acc[ii][jj*4+1], alpha, bvals[jj*4+1]);
            v.z = fmaf(acc[ii][jj*4+2], alpha, bvals[jj*4+2]);
            v.w = fmaf(acc[ii][jj*4+3], alpha, bvals[jj*4+3]);
            if (mode == 0){
                *(float4*)(C + (size_t)r * N + c) = v;
            } else if (mode == 1){
                int b = r >> 11, s = r & 2047;
                int h = c >> 6,  hd = c & 63;
                *(float4*)(C + (((size_t)(b * NHEAD + h) * SEQ + s) << 6) + hd) = v;
            } else {
                int b = r >> 11, s = r & 2047;
                int h = c >> 6,  hd = c & 63;
                size_t base = (((size_t)(b * NHEAD + h) * SEQ + s) << 6) + hd;
                if (b < 2){
                    float vv[4] = {v.x, v.y, v.z, v.w};
                    __nv_bfloat16 hi[4], mi[4], lo[4];
#pragma unroll
                    for (int j = 0; j < 4; j++){
                        float f = vv[j];
                        hi[j] = __float2bfloat16(f);
                        float r1 = f - __bfloat162float(hi[j]);
                        mi[j] = __float2bfloat16(r1);
                        float r2 = r1 - __bfloat162float(mi[j]);
                        lo[j] = __float2bfloat16(r2);
                    }
                    *(__nv_bfloat162*)(o1 + base)     = __nv_bfloat162(hi[0], hi[1]);
                    *(__nv_bfloat162*)(o1 + base + 2) = __nv_bfloat162(hi[2], hi[3]);
                    *(__nv_bfloat162*)(o2 + base)     = __nv_bfloat162(mi[0], mi[1]);
                    *(__nv_bfloat162*)(o2 + base + 2) = __nv_bfloat162(mi[2], mi[3]);
                    *(__nv_bfloat162*)(o3 + base)     = __nv_bfloat162(lo[0], lo[1]);
                    *(__nv_bfloat162*)(o3 + base + 2) = __nv_bfloat162(lo[2], lo[3]);
                } else {
                    *(float4*)(C + base) = v;
                }
            }
        }
    }
}

__global__ void __launch_bounds__(256, 2) qkv_kernel(
    const float* __restrict__ x,
    const float* __restrict__ Wq, const float* __restrict__ bq,
    const float* __restrict__ Wk, const float* __restrict__ bk,
    const float* __restrict__ Wv, const float* __restrict__ bv,
    __nv_bfloat16* Qh, __nv_bfloat16* Qm, __nv_bfloat16* Ql,
    __nv_bfloat16* Kh, __nv_bfloat16* Km, __nv_bfloat16* Kl,
    float* Qf, float* Kf, float* Vp)
{
    int z = blockIdx.z;
    int m0 = blockIdx.y * 128, n0 = blockIdx.x * 128;
    if (z == 0){
        gemm_tile(x, Wq, bq, Qf, DIM, DIM, 0.125f, 0.125f, m0, n0, 2, Qh, Qm, Ql);
    } else if (z == 1){
        gemm_tile(x, Wk, bk, Kf, DIM, DIM, 1.f, 1.f, m0, n0, 2, Kh, Km, Kl);
    } else {
        gemm_tile(x, Wv, bv, Vp, DIM, DIM, 1.f, 1.f, m0, n0, 1, nullptr, nullptr, nullptr);
    }
}

// =====================================================================
// 128x64 SGEMM tile for the out-projection (BM=128 keeps A-reuse; BN=64
// doubles block count -> 256 blocks = better wave fill). Each output
// element keeps the identical k-ordered fma2 chain -> bit-identical.
// =====================================================================
__global__ void __launch_bounds__(256) gemm_n64_kernel(
    const float* __restrict__ A, const float* __restrict__ B,
    const float* __restrict__ bias, float* __restrict__ C,
    int K, int N, float alpha)
{
    __shared__ float As[32][132];
    __shared__ float Bs[32][68];
    const int tid = threadIdx.x;
    const int tx = tid & 15, ty = tid >> 4;
    const int lm = tid >> 1, lk4 = tid & 1;       // A loader: 128 rows
    const int lb = tid >> 2, lkb = tid & 3;       // B loader: 64 rows
    const int m0 = blockIdx.y * 128, n0 = blockIdx.x * 64;

    const float* Ag = A + (size_t)(m0 + lm) * K + lk4 * 4;
    const float* Bg = B + (size_t)(n0 + lb) * K + lkb * 4;

    float4 pa[4], pb[2];
#pragma unroll
    for (int kk = 0; kk < 4; kk++) pa[kk] = *(const float4*)(Ag + kk * 8);
#pragma unroll
    for (int kk = 0; kk < 2; kk++) pb[kk] = *(const float4*)(Bg + kk * 16);

    unsigned long long acc2[8][2];
#pragma unroll
    for (int i = 0; i < 8; i++)
#pragma unroll
        for (int j = 0; j < 2; j++) acc2[i][j] = 0ull;

    int k0 = 0;
    for (;;){
        __syncthreads();
#pragma unroll
        for (int kk = 0; kk < 4; kk++){
            int kc = lk4 * 4 + kk * 8;
            As[kc+0][lm] = pa[kk].x; As[kc+1][lm] = pa[kk].y;
            As[kc+2][lm] = pa[kk].z; As[kc+3][lm] = pa[kk].w;
        }
#pragma unroll
        for (int kk = 0; kk < 2; kk++){
            int kc = lkb * 4 + kk * 16;
            Bs[kc+0][lb] = pb[kk].x; Bs[kc+1][lb] = pb[kk].y;
            Bs[kc+2][lb] = pb[kk].z; Bs[kc+3][lb] = pb[kk].w;
        }
        __syncthreads();
        k0 += 32;
        if (k0 < K){
#pragma unroll
            for (int kk = 0; kk < 4; kk++) pa[kk] = *(const float4*)(Ag + k0 + kk * 8);
#pragma unroll
            for (int kk = 0; kk < 2; kk++) pb[kk] = *(const float4*)(Bg + k0 + kk * 16);
        }
#pragma unroll
        for (int kk = 0; kk < 32; kk++){
            float4 a0 = *(const float4*)&As[kk][ty * 4];
            float4 a1 = *(const float4*)&As[kk][64 + ty * 4];
            ulonglong2 b0 = *(const ulonglong2*)&Bs[kk][tx * 4];
            unsigned long long bv[2] = {b0.x, b0.y};
            float avf[8] = {a0.x, a0.y, a0.z, a0.w, a1.x, a1.y, a1.z, a1.w};
            unsigned long long av[8];
#pragma unroll
            for (int i = 0; i < 8; i++) av[i] = packdup(avf[i]);
#pragma unroll
            for (int i = 0; i < 8; i++)
#pragma unroll
                for (int j = 0; j < 2; j++)
                    fma2(acc2[i][j], av[i], bv[j]);
        }
        if (k0 >= K) break;
    }

    float acc[8][4];
#pragma unroll
    for (int i = 0; i < 8; i++)
#pragma unroll
        for (int j = 0; j < 2; j++)
            unpack2(acc2[i][j], acc[i][2*j], acc[i][2*j+1]);

    float bvals[4];
    {
        int c = n0 + tx * 4;
        float4 bb = *(const float4*)(bias + c);
        bvals[0] = bb.x; bvals[1] = bb.y; bvals[2] = bb.z; bvals[3] = bb.w;
    }
#pragma unroll
    for (int ii = 0; ii < 8; ii++){
        int r = m0 + ((ii < 4) ? (ty * 4 + ii) : (64 + ty * 4 + ii - 4));
        int c = n0 + tx * 4;
        float4 v;
        v.x = fmaf(acc[ii][0], alpha, bvals[0]);
        v.y = fmaf(acc[ii][1], alpha, bvals[1]);
        v.z = fmaf(acc[ii][2], alpha, bvals[2]);
        v.w = fmaf(acc[ii][3], alpha, bvals[3]);
        *(float4*)(C + (size_t)r * N + c) = v;
    }
}

// =====================================================================
// stage-1 mean over seq; gate kernel finishes the mean + computes gproj
// =====================================================================
__global__ void mean1_kernel(const float* __restrict__ x, float* __restrict__ part)
{
    int b = blockIdx.x, c = blockIdx.y, t = threadIdx.x;
    const float* p = x + ((size_t)b * SEQ + c * 128) * DIM + t;
    float s = 0.f;
    for (int i = 0; i < 128; i++) s += p[(size_t)i * DIM];
    part[(b * 16 + c) * DIM + t] = s;
}

__global__ void gate_kernel(const float* __restrict__ part,
    const float* __restrict__ Wg, const float* __restrict__ bg,
    const float* __restrict__ Wgp, const float* __restrict__ bgp,
    float* __restrict__ gproj)
{
    __shared__ float xm[BATCH * DIM];
    __shared__ float gg[BATCH][16];
    int t = threadIdx.x;
    for (int idx = t; idx < BATCH * DIM; idx += 256){
        int b = idx >> 8, d = idx & 255;
        float s = 0.f;
#pragma unroll
        for (int i = 0; i < 16; i++) s += part[(b * 16 + i) * DIM + d];
        xm[idx] = s * (1.0f / SEQ);
    }
    __syncthreads();
    if (t < BATCH * 16){
        int b = t >> 4, j = t & 15;
        const float* x0 = xm + b * DIM;
        const float* w  = Wg + j * DIM;
        float s = bg[j];
        for (int d = 0; d < DIM; d++) s = fmaf(x0[d], w[d], s);
        gg[b][j] = 1.f / (1.f + expf(-s));
    }
    __syncthreads();
    for (int idx = t; idx < BATCH * DIM; idx += 256){
        int b = idx >> 8, d = idx & 255;
        const float* w = Wgp + d * 16;
        float s = bgp[d];
#pragma unroll
        for (int j = 0; j < 16; j++) s = fmaf(gg[b][j], w[j], s);
        gproj[idx] = s;
    }
}

// =====================================================================
// per-row: quantile threshold -> masked softmax -> sparse att = p @ V
//          -> fused distill+gate mix (head-local, 16-wide groups).
// =====================================================================
__global__ void __launch_bounds__(256) attn_row_kernel(
    const float* __restrict__ scores,
    const float* __restrict__ V,
    const float* __restrict__ Wd, const float* __restrict__ bd,
    const float* __restrict__ gproj,
    float* __restrict__ mixed)
{
    __shared__ float pv[SEQ];
    __shared__ unsigned short idxs[SEQ];
    __shared__ int hist[256];
    __shared__ int wsum[8];
    __shared__ float fred[8];
    __shared__ float accbuf[8][64];
    __shared__ float arow[64];
    __shared__ int s_bin, s_rem;
    __shared__ float s_slo, s_max, s_sum;

    const int t = threadIdx.x, lane = t & 31, w = t >> 5;
    const int r = NROWS - 1 - blockIdx.x;
    const int q = r & (SEQ - 1), bh = r >> 11;

    const float4* row4 = (const float4*)(scores + (size_t)r * SEQ);
    float4 f0 = row4[t], f1 = row4[256 + t];
    float sv[8] = {f0.x, f0.y, f0.z, f0.w, f1.x, f1.y, f1.z, f1.w};
    unsigned kv[8];
#pragma unroll
    for (int i = 0; i < 8; i++) kv[i] = f2k(sv[i]);

    float lmax = sv[0];
#pragma unroll
    for (int i = 1; i < 8; i++) lmax = fmaxf(lmax, sv[i]);
#pragma unroll
    for (int o = 16; o; o >>= 1)
        lmax = fmaxf(lmax, __shfl_xor_sync(0xffffffffu, lmax, o));
    if (lane == 0) fred[w] = lmax;
    __syncthreads();
    if (t == 0){
        float m = fred[0];
#pragma unroll
        for (int i = 1; i < 8; i++) m = fmaxf(m, fred[i]);
        s_max = m;
    }

    // ---- radix select: value of rank-205 (205th largest) ----
    unsigned prefix = 0;
    int rem = 205;
#pragma unroll
    for (int shift = 24; shift >= 0; shift -= 8){
        hist[t] = 0;
        __syncthreads();
        unsigned himask = (shift == 24) ? 0u : (0xFFFFFFFFu << (shift + 8));
#pragma unroll
        for (int i = 0; i < 8; i++){
            if ((kv[i] & himask) == prefix)
                atomicAdd(&hist[(kv[i] >> shift) & 0xFFu], 1);
        }
        __syncthreads();
        int u = 255 - t;
        int s = hist[u];
#pragma unroll
        for (int o = 1; o < 32; o <<= 1){
            int n = __shfl_up_sync(0xffffffffu, s, o);
            if (lane >= o) s += n;
        }
        if (lane == 31) wsum[w] = s;
        __syncthreads();
        int off = 0;
#pragma unroll
        for (int i = 0; i < 8; i++) if (i < w) off += wsum[i];
        int pprev = __shfl_up_sync(0xffffffffu, s, 1);
        int nxt = (lane > 0) ? (off + pprev) : off;
        int sfx = off + s;
        if (sfx >= rem && nxt < rem){ s_bin = u; s_rem = rem - nxt; }
        __syncthreads();
        prefix |= ((unsigned)s_bin) << shift;
        rem = s_rem;
    }
    float shi = k2f(prefix);

    // ---- rank-206: count >= shi; max < shi ----
    int cge = 0;
    float lmlt = -3.4e38f;
#pragma unroll
    for (int i = 0; i < 8; i++){
        if (sv[i] >= shi) cge++;
        else lmlt = fmaxf(lmlt, sv[i]);
    }
#pragma unroll
    for (int o = 16; o; o >>= 1){
        cge  += __shfl_xor_sync(0xffffffffu, cge, o);
        lmlt  = fmaxf(lmlt, __shfl_xor_sync(0xffffffffu, lmlt, o));
    }
    if (lane == 0){ hist[w] = cge; fred[w] = lmlt; }
    __syncthreads();
    if (t == 0){
        int c = 0; float m = -3.4e38f;
#pragma unroll
        for (int i = 0; i < 8; i++){ c += hist[i]; m = fmaxf(m, fred[i]); }
        s_slo = (c >= 206) ? shi : m;
    }
    __syncthreads();
    float slo = s_slo;
    const float idxf = 0.9f * 2047.0f;
    const float frac = idxf - 1842.0f;
    float thr = slo + frac * (shi - slo);
    float rowmax = s_max;

    // ---- exp + deterministic compaction ----
    float ev[8];
    unsigned kmask = 0;
    int kcnt = 0;
    float lsum = 0.f;
#pragma unroll
    for (int i = 0; i < 8; i++){
        ev[i] = 0.f;
        if (sv[i] >= thr){
            float e = expf(sv[i] - rowmax);
            ev[i] = e; lsum += e;
            kmask |= (1u << i); kcnt++;
        }
    }
    int ps = kcnt;
#pragma unroll
    for (int o = 1; o < 32; o <<= 1){
        int n = __shfl_up_sync(0xffffffffu, ps, o);
        if (lane >= o) ps += n;
    }
    if (lane == 31) wsum[w] = ps;
#pragma unroll
    for (int o = 16; o; o >>= 1)
        lsum += __shfl_xor_sync(0xffffffffu, lsum, o);
    if (lane == 0) fred[w] = lsum;
    __syncthreads();
    int off = 0, tot = 0;
#pragma unroll
    for (int i = 0; i < 8; i++){ if (i < w) off += wsum[i]; tot += wsum[i]; }
    int pos = off + ps - kcnt;
#pragma unroll
    for (int i = 0; i < 8; i++){
        if (kmask & (1u << i)){
            idxs[pos] = (unsigned short)((i < 4) ? (4 * t + i) : (1024 + 4 * t + i - 4));
            pv[pos] = ev[i];
            pos++;
        }
    }
    if (t == 0){
        float ss = 0.f;
#pragma unroll
        for (int i = 0; i < 8; i++) ss += fred[i];
        s_sum = ss;
    }
    __syncthreads();

    // ---- sparse att: 8 warps, float2 per lane, 8-way unrolled gather ----
    const float inv = 1.0f / s_sum;
    const float2* Vh2 = (const float2*)(V + (size_t)bh * SEQ * HDIM);
    float a0 = 0.f, a1 = 0.f, a2 = 0.f, a3 = 0.f;
    float a4 = 0.f, a5 = 0.f, a6 = 0.f, a7 = 0.f;
    int j = w;
    for (; j + 56 < tot; j += 64){
        float p[8];
        unsigned ix[8];
#pragma unroll
        for (int u = 0; u < 8; u++){
            p[u]  = pv[j + 8 * u];
            ix[u] = idxs[j + 8 * u];
        }
        float2 v[8];
#pragma unroll
        for (int u = 0; u < 8; u++)
            v[u] = Vh2[ix[u] * 32 + lane];
        a0 += p[0] * v[0].x; a1 += p[0] * v[0].y;
        a2 += p[1] * v[1].x; a3 += p[1] * v[1].y;
        a4 += p[2] * v[2].x; a5 += p[2] * v[2].y;
        a6 += p[3] * v[3].x; a7 += p[3] * v[3].y;
        a0 += p[4] * v[4].x; a1 += p[4] * v[4].y;
        a2 += p[5] * v[5].x; a3 += p[5] * v[5].y;
        a4 += p[6] * v[6].x; a5 += p[6] * v[6].y;
        a6 += p[7] * v[7].x; a7 += p[7] * v[7].y;
    }
    for (; j < tot; j += 8){
        float pp = pv[j];
        float2 vr = Vh2[(unsigned)idxs[j] * 32 + lane];
        a0 += pp * vr.x;
        a1 += pp * vr.y;
    }
    a0 += a2 + a4 + a6;
    a1 += a3 + a5 + a7;
    accbuf[w][2 * lane]     = a0;
    accbuf[w][2 * lane + 1] = a1;
    __syncthreads();
    if (t < 64){
        float tt = 0.f;
#pragma unroll
        for (int w2 = 0; w2 < 8; w2++) tt += accbuf[w2][t];
        arow[t] = tt * inv;
    }
    __syncthreads();

    // ---- fused distill + gate mix (16-wide groups are head-local) ----
    if (t < 64){
        const int h = bh & (NHEAD - 1), b = bh >> 2;
        const int g16 = (t >> 4) << 4;
        const int jrow = t & 15;
        float s = bd[jrow];
#pragma unroll
        for (int j2 = 0; j2 < 16; j2++)
            s = fmaf(arow[g16 + j2], Wd[jrow * 16 + j2], s);
        float av = arow[t];
        float g = gproj[b * DIM + h * HDIM + t];
        mixed[((size_t)b * SEQ + q) * DIM + h * HDIM + t] = g * s + (1.f - g) * av;
    }
}

// ---- persistent side stream + events (created on first, uncaptured call) ----
static cudaStream_t g_side = nullptr;
static cudaEvent_t g_ev[2];
static int g_ok = 0;

// =====================================================================
extern "C" void kernel_launch(void* const* d_in, const int* in_sizes, int n_in,
                              void* d_out, int out_size)
{
    (void)in_sizes; (void)n_in; (void)out_size;
    const float* x   = (const float*)d_in[0];
    const float* Wq  = (const float*)d_in[1];
    const float* bq  = (const float*)d_in[2];
    const float* Wk  = (const float*)d_in[3];
    const float* bk  = (const float*)d_in[4];
    const float* Wv  = (const float*)d_in[5];
    const float* bv  = (const float*)d_in[6];
    const float* Wd  = (const float*)d_in[7];
    const float* bd  = (const float*)d_in[8];
    const float* Wg  = (const float*)d_in[9];
    const float* bg  = (const float*)d_in[10];
    const float* Wgp = (const float*)d_in[11];
    const float* bgp = (const float*)d_in[12];
    const float* Wo  = (const float*)d_in[13];
    const float* bo  = (const float*)d_in[14];
    float* out = (float*)d_out;

    __nv_bfloat16 *pQh, *pQm, *pQl, *pKh, *pKm, *pKl;
    float *pQf, *pKf, *pV, *pS, *pMix, *pGp, *pMp;
    cudaGetSymbolAddress((void**)&pQh, g_Qh);
    cudaGetSymbolAddress((void**)&pQm, g_Qm);
    cudaGetSymbolAddress((void**)&pQl, g_Ql);
    cudaGetSymbolAddress((void**)&pKh, g_Kh);
    cudaGetSymbolAddress((void**)&pKm, g_Km);
    cudaGetSymbolAddress((void**)&pKl, g_Kl);
    cudaGetSymbolAddress((void**)&pQf, g_Qf);
    cudaGetSymbolAddress((void**)&pKf, g_Kf);
    cudaGetSymbolAddress((void**)&pV,   g_V);
    cudaGetSymbolAddress((void**)&pS,   g_scores);
    cudaGetSymbolAddress((void**)&pMix, g_mixed);
    cudaGetSymbolAddress((void**)&pGp,  g_gproj);
    cudaGetSymbolAddress((void**)&pMp,  g_mpart);

    cudaFuncSetAttribute(scores_hybrid_kernel,
                         cudaFuncAttributeMaxDynamicSharedMemorySize, SMMA_SMEM);

    // one-time side-stream/event setup (runs on the uncaptured correctness call)
    cudaStreamCaptureStatus cap = cudaStreamCaptureStatusNone;
    cudaStreamIsCapturing((cudaStream_t)0, &cap);
    if (!g_side && cap == cudaStreamCaptureStatusNone){
        int ok = 1;
        if (cudaStreamCreateWithFlags(&g_side, cudaStreamNonBlocking) != cudaSuccess) ok = 0;
        for (int i = 0; ok && i < 2; i++)
            if (cudaEventCreateWithFlags(&g_ev[i], cudaEventDisableTiming) != cudaSuccess) ok = 0;
        g_ok = ok;
        if (!ok) g_side = nullptr;
    }
    const int overlap = (g_ok && g_side);

    if (overlap){
        // fork: gate path (tiny) runs on side stream, overlapped with qkv
        cudaEventRecord(g_ev[0], (cudaStream_t)0);
        cudaStreamWaitEvent(g_side, g_ev[0], 0);
        mean1_kernel<<<dim3(BATCH, 16), 256, 0, g_side>>>(x, pMp);
        gate_kernel<<<1, 256, 0, g_side>>>(pMp, Wg, bg, Wgp, bgp, pGp);
        cudaEventRecord(g_ev[1], g_side);
    } else {
        mean1_kernel<<<dim3(BATCH, 16), 256>>>(x, pMp);
        gate_kernel<<<1, 256>>>(pMp, Wg, bg, Wgp, bgp, pGp);
    }

    qkv_kernel<<<dim3(DIM / 128, (BATCH * SEQ) / 128, 3), 256>>>(
        x, Wq, bq, Wk, bk, Wv, bv, pQh, pQm, pQl, pKh, pKm, pKl, pQf, pKf, pV);

    scores_hybrid_kernel<<<dim3(32, 16, 8), 256, SMMA_SMEM>>>(
        pQh, pQm, pQl, pKh, pKm, pKl, pQf, pKf, pS);

    if (overlap) cudaStreamWaitEvent((cudaStream_t)0, g_ev[1], 0);   // join gate
    attn_row_kernel<<<NROWS, 256>>>(pS, pV, Wd, bd, pGp, pMix);

    gemm_n64_kernel<<<dim3(DIM / 64, (BATCH * SEQ) / 128), 256>>>(
        pMix, Wo, bo, out, DIM, DIM, 1.f);
}